// round 7
// baseline (speedup 1.0000x reference)
#include <cuda_runtime.h>

// GCN: out = spmm(w, relu(spmm(w, x@W1^T) + b1) @ W2^T) + b2
// using the commutation spmm(h)@W^T == spmm(h@W^T)  (layer-2 SpMM over 40
// feats instead of 128 -> 3.2x less gather traffic).
//
// edge_index dtype is detected at runtime (int32 vs int64): JAX silently
// downgrades int64->int32 unless x64 is enabled, and reading int32 data as
// int64 produced garbage indices -> device trap 717 in rounds 4/6.
//
// Pipeline (all scratch in __device__ globals, device-side refs only):
//  0. detect edge_index dtype (1 thread)
//  1. deg/count (atomics over E)
//  2. dinv = rsqrt(deg)
//  3. single-block exclusive scan of counts -> row_ptr (+cursor copy)
//  4. CSR scatter: col_perm, w_perm  (w = dinv[row]*C*dinv[col])
//  5. y1 = x @ W1^T     (fp32 smem GEMM, 64 nodes x 128 cols, k-chunked W)
//  6. h  = relu(csr_spmm(y1)+b1)   (gather-only, warp/row, float4 lanes)
//  7. y2 = h @ W2^T     (same GEMM, 40 cols padded to 64)
//  8. out = csr_spmm(y2) + b2      (gather-only, 40 feats)

#define NMAX 100000
#define EMAX 1600000

__device__ int   g_is64;
__device__ float g_deg[NMAX];            // degree, then dinv (in place)
__device__ int   g_cnt[NMAX];
__device__ int   g_rowptr[NMAX + 1];
__device__ int   g_cursor[NMAX];
__device__ int   g_colp[EMAX];
__device__ float g_wp[EMAX];
__device__ __align__(16) float g_y1[(size_t)NMAX * 128];
__device__ __align__(16) float g_h [(size_t)NMAX * 128];
__device__ __align__(16) float g_y2[(size_t)NMAX * 40];

// read edge index e from row (part==0) or col (part==1) stream
__device__ __forceinline__ int edge_at(const void* ei, int E, int part, int e,
                                       int is64) {
    if (is64) return (int)((const long long*)ei)[(size_t)part * E + e];
    return ((const int*)ei)[(size_t)part * E + e];
}

// -------------------------------------------------- dtype detector (1 thr)
__global__ void k_detect(const void* ei, int E) {
    // int64 indices are < NMAX; int32 pairs read as int64 are >= 2^32
    // unless the high half is exactly 0 (prob ~1e-5 per element; check 8).
    const long long* p = (const long long*)ei;
    int ok = 1;
    int m = (E < 8) ? E : 8;
    for (int i = 0; i < m; i++) {
        long long v = p[i];
        if (v < 0 || v >= NMAX) ok = 0;
    }
    g_is64 = ok;
}

// ---------------------------------------------------------------- zero
__global__ void k_zero(int n) {
    int i = blockIdx.x * blockDim.x + threadIdx.x;
    if (i < n) { g_deg[i] = 0.0f; g_cnt[i] = 0; }
}

// ------------------------------------------------------- degree + count
__global__ void k_deg_count(const void* __restrict__ ei,
                            const float* __restrict__ cv, int E) {
    int e = blockIdx.x * blockDim.x + threadIdx.x;
    if (e >= E) return;
    int is64 = g_is64;
    int r = edge_at(ei, E, 0, e, is64);
    atomicAdd(&g_deg[r], cv[e]);
    atomicAdd(&g_cnt[r], 1);
}

// ----------------------------------------------------------------- dinv
__global__ void k_dinv(int n) {
    int i = blockIdx.x * blockDim.x + threadIdx.x;
    if (i < n) {
        float d = g_deg[i];
        g_deg[i] = (d > 0.0f) ? rsqrtf(d) : 0.0f;
    }
}

// -------------------------------------------- single-block exclusive scan
__global__ void k_scan(int n) {
    __shared__ int warp_sums[32];
    __shared__ int carry_s;
    int tid = threadIdx.x;
    if (tid == 0) carry_s = 0;
    __syncthreads();
    int lane = tid & 31, w = tid >> 5;
    for (int base = 0; base < n; base += blockDim.x) {
        int i = base + tid;
        int v = (i < n) ? g_cnt[i] : 0;
        int s = v;
        #pragma unroll
        for (int o = 1; o < 32; o <<= 1) {
            int t = __shfl_up_sync(0xFFFFFFFFu, s, o);
            if (lane >= o) s += t;
        }
        if (lane == 31) warp_sums[w] = s;
        __syncthreads();
        if (w == 0) {
            int ws = warp_sums[lane];
            #pragma unroll
            for (int o = 1; o < 32; o <<= 1) {
                int t = __shfl_up_sync(0xFFFFFFFFu, ws, o);
                if (lane >= o) ws += t;
            }
            warp_sums[lane] = ws;
        }
        __syncthreads();
        int incl = s + (w > 0 ? warp_sums[w - 1] : 0) + carry_s;
        int excl = incl - v;
        if (i < n) { g_rowptr[i] = excl; g_cursor[i] = excl; }
        __syncthreads();
        if (tid == blockDim.x - 1) carry_s = incl;
        __syncthreads();
    }
    if (tid == 0) g_rowptr[n] = carry_s;
}

// -------------------------------------------------------- CSR scatter + w
__global__ void k_scatter(const void* __restrict__ ei,
                          const float* __restrict__ cv, int E) {
    int e = blockIdx.x * blockDim.x + threadIdx.x;
    if (e >= E) return;
    int is64 = g_is64;
    int r = edge_at(ei, E, 0, e, is64);
    int c = edge_at(ei, E, 1, e, is64);
    float wv = g_deg[r] * cv[e] * g_deg[c];
    int pos = atomicAdd(&g_cursor[r], 1);
    g_colp[pos] = c;
    g_wp[pos]   = wv;
}

// ---------------------------------------------------------- dense GEMM
// Y[n, c] = sum_k X[n,k] * W[c,k].
// Block: 64 nodes, 256 threads (8 warps). Warp handles 8 nodes; lane handles
// cols lane + 32*j, j < HT. W tile loaded in k-chunks of 16 (stride 17 ->
// conflict-free: gcd(17,32)=1). x tile stride 128 is fine: reads are
// lane-invariant broadcasts. Static smem: 32KB + HT*32*17*4 <= 40.7KB.
// LAYER==1: X = Xin param, Y = g_y1. LAYER==2: X = g_h, Y = g_y2.
template <int HT, int LAYER>
__global__ void k_gemm(const float* __restrict__ Xin,
                       const float* __restrict__ W, int N, int Hreal) {
    __shared__ float xs[64 * 128];
    __shared__ float ws[HT * 32 * 17];
    const float* X = (LAYER == 1) ? Xin : (const float*)g_h;
    float*       Y = (LAYER == 1) ? g_y1 : g_y2;

    int tid = threadIdx.x;
    int nb = blockIdx.x * 64;

    for (int i = tid; i < 64 * 128; i += 256) {
        int n = i >> 7;
        xs[i] = (nb + n < N) ? X[(size_t)nb * 128 + i] : 0.0f;
    }

    int lane = tid & 31, wid = tid >> 5;
    float acc[8][HT];
    #pragma unroll
    for (int i = 0; i < 8; i++)
        #pragma unroll
        for (int j = 0; j < HT; j++) acc[i][j] = 0.0f;

    for (int kb = 0; kb < 128; kb += 16) {
        __syncthreads();
        for (int i = tid; i < HT * 32 * 16; i += 256) {
            int hh = i >> 4, kk = i & 15;
            ws[hh * 17 + kk] = (hh < Hreal) ? W[(size_t)hh * 128 + kb + kk] : 0.0f;
        }
        __syncthreads();

        #pragma unroll
        for (int kk = 0; kk < 16; kk++) {
            float wf[HT];
            #pragma unroll
            for (int j = 0; j < HT; j++) wf[j] = ws[(lane + 32 * j) * 17 + kk];
            #pragma unroll
            for (int i = 0; i < 8; i++) {
                float xf = xs[(wid * 8 + i) * 128 + kb + kk];
                #pragma unroll
                for (int j = 0; j < HT; j++)
                    acc[i][j] = fmaf(xf, wf[j], acc[i][j]);
            }
        }
    }

    #pragma unroll
    for (int i = 0; i < 8; i++) {
        int n = nb + wid * 8 + i;
        if (n < N) {
            #pragma unroll
            for (int j = 0; j < HT; j++) {
                int c = lane + 32 * j;
                if (c < Hreal) Y[(size_t)n * Hreal + c] = acc[i][j];
            }
        }
    }
}

// ---------------------------------------- CSR SpMM, 128 feats, bias+relu
// reads g_y1, writes g_h
__global__ void k_spmm128(const float* __restrict__ bias, int N) {
    int wid = threadIdx.x >> 5, lane = threadIdx.x & 31;
    int r = blockIdx.x * 8 + wid;
    if (r >= N) return;
    const float4* feat = (const float4*)g_y1;
    int e0 = g_rowptr[r], e1 = g_rowptr[r + 1];
    float4 acc = make_float4(0.f, 0.f, 0.f, 0.f);
    for (int e = e0; e < e1; e++) {
        int c = g_colp[e];
        float wv = g_wp[e];
        float4 v = feat[(size_t)c * 32 + lane];
        acc.x = fmaf(wv, v.x, acc.x);
        acc.y = fmaf(wv, v.y, acc.y);
        acc.z = fmaf(wv, v.z, acc.z);
        acc.w = fmaf(wv, v.w, acc.w);
    }
    float4 b = ((const float4*)bias)[lane];
    acc.x = fmaxf(acc.x + b.x, 0.f);
    acc.y = fmaxf(acc.y + b.y, 0.f);
    acc.z = fmaxf(acc.z + b.z, 0.f);
    acc.w = fmaxf(acc.w + b.w, 0.f);
    ((float4*)g_h)[(size_t)r * 32 + lane] = acc;
}

// -------------------------------------------- CSR SpMM, 40 feats, + bias
// reads g_y2, writes out
__global__ void k_spmm40(const float* __restrict__ bias,
                         float* __restrict__ out, int N) {
    int wid = threadIdx.x >> 5, lane = threadIdx.x & 31;
    int r = blockIdx.x * 8 + wid;
    if (r >= N) return;
    int e0 = g_rowptr[r], e1 = g_rowptr[r + 1];
    float a0 = 0.f, a1 = 0.f;
    for (int e = e0; e < e1; e++) {
        int c = g_colp[e];
        float wv = g_wp[e];
        const float* f = g_y2 + (size_t)c * 40;
        a0 = fmaf(wv, f[lane], a0);
        if (lane < 8) a1 = fmaf(wv, f[32 + lane], a1);
    }
    out[(size_t)r * 40 + lane] = a0 + bias[lane];
    if (lane < 8) out[(size_t)r * 40 + 32 + lane] = a1 + bias[32 + lane];
}

// ----------------------------------------------------------------- host
extern "C" void kernel_launch(void* const* d_in, const int* in_sizes, int n_in,
                              void* d_out, int out_size) {
    const float* x  = (const float*)d_in[0];
    const void*  ei = d_in[1];                 // int32 or int64, detected
    const float* cv = (const float*)d_in[2];
    const float* W1 = (const float*)d_in[3];
    const float* b1 = (const float*)d_in[4];
    const float* W2 = (const float*)d_in[5];
    const float* b2 = (const float*)d_in[6];
    float* out = (float*)d_out;

    int N = in_sizes[0] / 128;
    int E = in_sizes[2];

    int gn = (N + 255) / 256;
    int ge = (E + 255) / 256;

    k_detect<<<1, 1>>>(ei, E);
    k_zero<<<gn, 256>>>(N);
    k_deg_count<<<ge, 256>>>(ei, cv, E);
    k_dinv<<<gn, 256>>>(N);
    k_scan<<<1, 1024>>>(N);
    k_scatter<<<ge, 256>>>(ei, cv, E);

    // GEMM1: y1 = x @ W1^T, 128 cols
    k_gemm<4, 1><<<(N + 63) / 64, 256>>>(x, W1, N, 128);

    // SpMM1 + bias + relu -> h
    k_spmm128<<<(N + 7) / 8, 256>>>(b1, N);

    // GEMM2: y2 = h @ W2^T, 40 cols (padded to 64 in-kernel)
    k_gemm<2, 2><<<(N + 63) / 64, 256>>>(nullptr, W2, N, 40);

    // SpMM2 + bias -> out
    k_spmm40<<<(N + 7) / 8, 256>>>(b2, out, N);
}